// round 7
// baseline (speedup 1.0000x reference)
#include <cuda_runtime.h>
#include <cstdint>
#include <cstddef>

#define NTOK   49
#define CDIM   128
#define HEADS  4
#define HD     32
#define XROW   136   // xs / O row stride (mod 32 == 8: conflict-free LDS.64)
#define QROW   40    // q/k row stride (mod 32 == 8)
#define VROW   56    // vt row stride (mod 32 == 24)
#define PROW   56    // P row stride  (mod 32 == 24)
#define WQROW  40    // qkv weight staging stride
#define WPROW  72    // proj weight staging stride (mod 32 == 8)
#define NTHR   1024

// shared-memory layout (float offsets) — every region offset is a multiple of 4 floats
#define OFF_XS   0                                  // 64*136  = 8704
#define OFF_Q    (OFF_XS + 64 * XROW)               // 4*64*40 = 10240
#define OFF_K    (OFF_Q + HEADS * 64 * QROW)        // 4*56*40 = 8960
#define OFF_VT   (OFF_K + HEADS * 56 * QROW)        // 4*32*56 = 7168
#define OFF_P    (OFF_VT + HEADS * HD * VROW)       // max(4*64*56=14336, 384*40=15360) = 15360
#define OFF_MASK (OFF_P + 15360)                    // 2401, padded to 2404
#define OFF_BIAS (OFF_MASK + 2404)                  // 676
#define OFF_RIDX (OFF_BIAS + 676)                   // 2401 ints
#define SMEM_FLOATS (OFF_RIDX + 2404)
#define SMEM_BYTES  (SMEM_FLOATS * 4)

__device__ __forceinline__ float tf32r(float x) {
    uint32_t u;
    asm("cvt.rna.tf32.f32 %0, %1;" : "=r"(u) : "f"(x));
    return __uint_as_float(u);
}

// logical col -> physical col within its 8-group: [0,4,1,5,2,6,3,7]
__device__ __forceinline__ int permc(int c) {
    return (c & ~7) | (((c & 3) << 1) | ((c >> 2) & 1));
}

__device__ __forceinline__ void mma8(float* d, const uint32_t* a, const uint32_t* b) {
    asm volatile(
        "mma.sync.aligned.m16n8k8.row.col.f32.tf32.tf32.f32 "
        "{%0,%1,%2,%3}, {%4,%5,%6,%7}, {%8,%9}, {%0,%1,%2,%3};\n"
        : "+f"(d[0]), "+f"(d[1]), "+f"(d[2]), "+f"(d[3])
        : "r"(a[0]), "r"(a[1]), "r"(a[2]), "r"(a[3]), "r"(b[0]), "r"(b[1]));
}

// A-fragment via two LDS.64 (ipair layout): rows (row, row+8), logical cols (kk+t, kk+t+4)
__device__ __forceinline__ void ldA(uint32_t* af, const float* base, int row, int stride, int kk2t) {
    float2 p0 = *(const float2*)(base + row * stride + kk2t);
    float2 p1 = *(const float2*)(base + (row + 8) * stride + kk2t);
    af[0] = __float_as_uint(p0.x);
    af[1] = __float_as_uint(p1.x);
    af[2] = __float_as_uint(p0.y);
    af[3] = __float_as_uint(p1.y);
}

__device__ __forceinline__ void ldB(uint32_t* bf, const float* base, int row, int stride, int kk2t) {
    float2 q = *(const float2*)(base + row * stride + kk2t);
    bf[0] = __float_as_uint(q.x);
    bf[1] = __float_as_uint(q.y);
}

// interleave 8 logical cols (two float4) into ipair physical order, with tf32 rounding
__device__ __forceinline__ void st_ipair8(float* dst, float4 lo, float4 hi) {
    float4 o0, o1;
    o0.x = tf32r(lo.x); o0.y = tf32r(hi.x); o0.z = tf32r(lo.y); o0.w = tf32r(hi.y);
    o1.x = tf32r(lo.z); o1.y = tf32r(hi.z); o1.z = tf32r(lo.w); o1.w = tf32r(hi.w);
    *(float4*)(dst)     = o0;
    *(float4*)(dst + 4) = o1;
}

__global__ __launch_bounds__(NTHR, 1)
void lpwin_kernel(const float* __restrict__ x,
                  const float* __restrict__ mask,
                  const float* __restrict__ qkv_w,
                  const float* __restrict__ proj_w,
                  const float* __restrict__ proj_b,
                  const float* __restrict__ bias_table,
                  const float* __restrict__ alpha,
                  const int*   __restrict__ rel_idx,
                  float* __restrict__ out,
                  int nwin)
{
    extern __shared__ float sm[];
    const int b    = blockIdx.x;
    const int tid  = threadIdx.x;
    const int wid  = tid >> 5;    // 0..31
    const int lane = tid & 31;
    const int g    = lane >> 2;   // mma groupID
    const int t    = lane & 3;    // mma threadID-in-group
    const int t2   = t << 1;      // ipair pair offset

    float* xs = sm + OFF_XS;
    float* Qs = sm + OFF_Q;
    float* Ks = sm + OFF_K;
    float* Vs = sm + OFF_VT;
    float* Ps = sm + OFF_P;
    float* Ws = sm + OFF_P;       // weight staging aliases P (live ranges disjoint)
    float* Ms = sm + OFF_MASK;
    float* Bt = sm + OFF_BIAS;
    int*   Ri = (int*)(sm + OFF_RIDX);

    // ---------------- Phase 1: stage inputs ----------------
    const float* xb = x + (size_t)b * (NTOK * CDIM);
    for (int i = tid; i < NTOK * 16; i += NTHR) {       // 8 cols per iter, ipair layout
        int r = i >> 4, c8 = (i & 15) << 3;
        float4 lo = *(const float4*)(xb + r * CDIM + c8);
        float4 hi = *(const float4*)(xb + r * CDIM + c8 + 4);
        st_ipair8(xs + r * XROW + c8, lo, hi);
    }
    for (int i = tid; i < (HEADS * HD * VROW) / 4; i += NTHR)
        *(float4*)(Vs + i * 4) = make_float4(0.f, 0.f, 0.f, 0.f);
    {
        // mask row base (widx*2401) is only 4B-aligned -> scalar copies
        const int widx = b % nwin;
        const float* mb = mask + (size_t)widx * (NTOK * NTOK);
        for (int i = tid; i < NTOK * NTOK; i += NTHR) Ms[i] = mb[i];
        for (int i = tid; i < 600; i += NTHR) *(int4*)(Ri + i * 4) = *(const int4*)(rel_idx + i * 4);
        if (tid == 0) Ri[2400] = rel_idx[2400];
    }
    for (int i = tid; i < 169; i += NTHR) *(float4*)(Bt + i * 4) = *(const float4*)(bias_table + i * 4);
    __syncthreads();

    // ---------------- Phase 2: QKV GEMM (tf32 mma), W streamed via smem (ipair) ----------------
    {
        float acc[6][4];
        #pragma unroll
        for (int nt = 0; nt < 6; ++nt)
            #pragma unroll
            for (int e = 0; e < 4; ++e) acc[nt][e] = 0.f;

        const int mt = wid >> 3;
        const int n0 = (wid & 7) * 48;
        for (int kc = 0; kc < 4; ++kc) {          // k-chunks of 32
            for (int i = tid; i < 384 * 4; i += NTHR) {     // 8 cols per iter
                int n = i >> 2, c8 = (i & 3) << 3;
                const float* src = qkv_w + n * CDIM + kc * 32 + c8;
                float4 lo = *(const float4*)(src);
                float4 hi = *(const float4*)(src + 4);
                st_ipair8(Ws + n * WQROW + c8, lo, hi);
            }
            __syncthreads();
            #pragma unroll
            for (int k8 = 0; k8 < 4; ++k8) {
                const int kp = k8 * 8 + t2;
                uint32_t af[4];
                ldA(af, xs, mt * 16 + g, XROW, kc * 32 + kp);
                #pragma unroll
                for (int nt = 0; nt < 6; ++nt) {
                    uint32_t bf[2];
                    ldB(bf, Ws, n0 + nt * 8 + g, WQROW, kp);
                    mma8(acc[nt], af, bf);
                }
            }
            __syncthreads();
        }
        // scatter C fragments to Q / K / V^T (k-dims stored ipair-permuted)
        #pragma unroll
        for (int nt = 0; nt < 6; ++nt)
            #pragma unroll
            for (int e = 0; e < 4; ++e) {
                int row = mt * 16 + g + (e >> 1) * 8;
                if (row >= NTOK) continue;
                int n = n0 + nt * 8 + 2 * t + (e & 1);
                float v = acc[nt][e];
                if (n < 128) {          // Q: head-dim col permuted
                    int col = permc(n & 31);
                    Qs[(n >> 5) * 64 * QROW + row * QROW + col] = v;
                } else if (n < 256) {   // K: head-dim col permuted
                    int m = n - 128;
                    int col = permc(m & 31);
                    Ks[(m >> 5) * 56 * QROW + row * QROW + col] = v;
                } else {                // V^T: token col permuted
                    int m = n - 256;
                    Vs[(m >> 5) * HD * VROW + (m & 31) * VROW + permc(row)] = tf32r(v);
                }
            }
    }
    __syncthreads();

    // ---------------- Phase 3: per-head attention (8 warps / head) ----------------
    const int h   = wid >> 3;
    const int sub = wid & 7;
    float* Qh = Qs + h * 64 * QROW;
    float* Kh = Ks + h * 56 * QROW;
    float* Vh = Vs + h * HD * VROW;
    float* Ph = Ps + h * 64 * PROW;

    // 3a: L2 normalize (permutation-invariant: sum over row); alpha folded into q_hat
    {
        const bool isQ = (sub < 4);
        const int  part = isQ ? sub : (sub - 4);
        const float sc = isQ ? alpha[h] : 1.f;
        float* T = isQ ? Qh : Kh;
        const int rs = part * 13;
        const int re = min(rs + 13, NTOK);
        for (int r = rs; r < re; r += 4) {
            float v[4], ss[4]; int rr[4];
            #pragma unroll
            for (int j = 0; j < 4; ++j) {
                rr[j] = min(r + j, re - 1);
                v[j]  = T[rr[j] * QROW + lane];
                ss[j] = v[j] * v[j];
            }
            #pragma unroll
            for (int o = 16; o > 0; o >>= 1) {
                #pragma unroll
                for (int j = 0; j < 4; ++j) ss[j] += __shfl_xor_sync(0xffffffffu, ss[j], o);
            }
            #pragma unroll
            for (int j = 0; j < 4; ++j) {
                if (r + j < re) {
                    float inv = sc / (sqrtf(ss[j]) + 1e-6f);
                    T[rr[j] * QROW + lane] = tf32r(v[j] * inv);
                }
            }
        }
    }
    __syncthreads();

    // 3b: S = alpha * q_hat k_hat^T + rpb + mask; pad cols j>=NTOK get -1e30 (exp -> 0)
    if (sub < 7) {
        const int nt = sub;
        uint32_t bfv[4][2];
        #pragma unroll
        for (int k8 = 0; k8 < 4; ++k8)
            ldB(bfv[k8], Kh, nt * 8 + g, QROW, k8 * 8 + t2);
        #pragma unroll
        for (int mt = 0; mt < 4; ++mt) {
            float c[4] = {0.f, 0.f, 0.f, 0.f};
            #pragma unroll
            for (int k8 = 0; k8 < 4; ++k8) {
                uint32_t af[4];
                ldA(af, Qh, mt * 16 + g, QROW, k8 * 8 + t2);
                mma8(c, af, bfv[k8]);
            }
            #pragma unroll
            for (int e = 0; e < 4; ++e) {
                int i = mt * 16 + g + (e >> 1) * 8;
                int j = nt * 8 + 2 * t + (e & 1);
                float v;
                if (j >= NTOK)       v = -1e30f;
                else if (i < NTOK)   v = c[e] + Bt[Ri[i * NTOK + j] * HEADS + h] + Ms[i * NTOK + j];
                else                 v = c[e];
                Ph[i * PROW + permc(j)] = v;
            }
        }
    }
    __syncthreads();

    // 3c: row softmax (no max-subtract: logits bounded); pads hold -1e30 -> exp 0
    {
        for (int i0 = sub; i0 < NTOK; i0 += 16) {
            const int ia = i0;
            const int ib = i0 + 8;
            const bool hasb = (ib < NTOK);
            const int ibc = hasb ? ib : ia;
            float e1a = __expf(Ph[ia * PROW + lane]);
            float e2a = (lane < 24) ? __expf(Ph[ia * PROW + 32 + lane]) : 0.f;
            float e1b = __expf(Ph[ibc * PROW + lane]);
            float e2b = (lane < 24) ? __expf(Ph[ibc * PROW + 32 + lane]) : 0.f;
            float sa = e1a + e2a;
            float sb = e1b + e2b;
            #pragma unroll
            for (int o = 16; o > 0; o >>= 1) {
                sa += __shfl_xor_sync(0xffffffffu, sa, o);
                sb += __shfl_xor_sync(0xffffffffu, sb, o);
            }
            float inva = 1.f / sa;
            Ph[ia * PROW + lane] = tf32r(e1a * inva);
            if (lane < 24) Ph[ia * PROW + 32 + lane] = tf32r(e2a * inva);
            if (hasb) {
                float invb = 1.f / sb;
                Ph[ib * PROW + lane] = tf32r(e1b * invb);
                if (lane < 24) Ph[ib * PROW + 32 + lane] = tf32r(e2b * invb);
            }
        }
    }
    __syncthreads();

    // 3d: O = P V (V^T layout): 1 n-tile x 2 m-tiles per warp; O -> xs (CDIM ipair)
    {
        const int nt  = sub >> 1;
        const int mt0 = (sub & 1) * 2;
        uint32_t bfv[7][2];
        #pragma unroll
        for (int k8 = 0; k8 < 7; ++k8)
            ldB(bfv[k8], Vh, nt * 8 + g, VROW, k8 * 8 + t2);
        #pragma unroll
        for (int mi = 0; mi < 2; ++mi) {
            const int mt = mt0 + mi;
            float c[4] = {0.f, 0.f, 0.f, 0.f};
            #pragma unroll
            for (int k8 = 0; k8 < 7; ++k8) {
                uint32_t af[4];
                ldA(af, Ph, mt * 16 + g, PROW, k8 * 8 + t2);
                mma8(c, af, bfv[k8]);
            }
            #pragma unroll
            for (int e = 0; e < 4; ++e) {
                int i = mt * 16 + g + (e >> 1) * 8;
                if (i >= NTOK) continue;
                int d = nt * 8 + 2 * t + (e & 1);
                xs[i * XROW + permc(h * HD + d)] = tf32r(c[e]);
            }
        }
    }
    __syncthreads();

    // ---------------- Phase 4: output projection + bias ----------------
    {
        float acc[2][4];
        #pragma unroll
        for (int mi = 0; mi < 2; ++mi)
            #pragma unroll
            for (int e = 0; e < 4; ++e) acc[mi][e] = 0.f;

        const int n0  = (wid & 15) * 8;
        const int mt0 = (wid >> 4) * 2;
        for (int kc = 0; kc < 2; ++kc) {          // k-chunks of 64
            for (int i = tid; i < 128 * 8; i += NTHR) {     // 8 cols per iter
                int n = i >> 3, c8 = (i & 7) << 3;
                const float* src = proj_w + n * CDIM + kc * 64 + c8;
                float4 lo = *(const float4*)(src);
                float4 hi = *(const float4*)(src + 4);
                st_ipair8(Ws + n * WPROW + c8, lo, hi);
            }
            __syncthreads();
            #pragma unroll
            for (int k8 = 0; k8 < 8; ++k8) {
                const int kp = k8 * 8 + t2;
                uint32_t bfv[2];
                ldB(bfv, Ws, n0 + g, WPROW, kp);
                #pragma unroll
                for (int mi = 0; mi < 2; ++mi) {
                    uint32_t af[4];
                    ldA(af, xs, (mt0 + mi) * 16 + g, XROW, kc * 64 + kp);
                    mma8(acc[mi], af, bfv);
                }
            }
            __syncthreads();
        }
        // stash into xs (logical layout, fresh live range), then coalesced store + bias
        #pragma unroll
        for (int mi = 0; mi < 2; ++mi)
            #pragma unroll
            for (int e = 0; e < 4; ++e) {
                int row = (mt0 + mi) * 16 + g + (e >> 1) * 8;
                if (row >= NTOK) continue;
                int col = n0 + 2 * t + (e & 1);
                xs[row * XROW + col] = acc[mi][e];
            }
        __syncthreads();
        float* ob = out + (size_t)b * (NTOK * CDIM);
        for (int i = tid; i < NTOK * 32; i += NTHR) {
            int r = i >> 5, c4 = (i & 31) << 2;
            float4 v  = *(const float4*)(xs + r * XROW + c4);
            float4 pb = *(const float4*)(proj_b + c4);
            v.x += pb.x; v.y += pb.y; v.z += pb.z; v.w += pb.w;
            *(float4*)(ob + r * CDIM + c4) = v;
        }
    }
}

extern "C" void kernel_launch(void* const* d_in, const int* in_sizes, int n_in,
                              void* d_out, int out_size) {
    const float* x    = (const float*)d_in[0];
    const float* mask = (const float*)d_in[1];
    const float* qkvw = (const float*)d_in[2];
    const float* pw   = (const float*)d_in[3];
    const float* pb   = (const float*)d_in[4];
    const float* bt   = (const float*)d_in[5];
    const float* al   = (const float*)d_in[6];
    const int*   ri   = (const int*)d_in[7];
    float* out = (float*)d_out;

    int B  = in_sizes[0] / (NTOK * CDIM);
    int NW = in_sizes[1] / (NTOK * NTOK);

    cudaFuncSetAttribute(lpwin_kernel, cudaFuncAttributeMaxDynamicSharedMemorySize, SMEM_BYTES);
    lpwin_kernel<<<B, NTHR, SMEM_BYTES>>>(x, mask, qkvw, pw, pb, bt, al, ri, out, NW);
}